// round 14
// baseline (speedup 1.0000x reference)
#include <cuda_runtime.h>
#include <cuda_bf16.h>
#include <cstdint>

// ---------------- problem constants ----------------
#define BATCH    256
#define FEAT     1500
#define FEAT_PAD 1536          // 96 * 16, padded K for decoder (zero-filled)
#define INSZ     28224
#define SPLITK   12
#define ENC_KBLK_TOTAL 1764    // 28224 / 16
#define ENC_KBLK_PER_SPLIT 147 // 12 * 147 = 1764 exactly
#define DEC_KBLK 96            // 1536 / 16

// ---------------- GEMM tile config -----------------
#define BM 128
#define BN 128
#define BK 16                  // K elements per chunk
#define NTH 256                // 8 warps: 2 (M) x 4 (N), warp tile 64x32

// smem: 4 tiles per stage (Ah, Al, Bh, Bl), each 128 rows x 16 bf16, row padded
// to 48B -> ldmatrix 8-row groups hit 8 distinct 16B segments (conflict-free)
#define ROWB   48
#define TILE_B (128 * ROWB)    // 6144
#define STAGE_B (4 * TILE_B)   // 24576
#define SMEM_TOTAL (2 * STAGE_B)  // 49152 -> 2 CTAs = 96KB/SM

#define OFF_AH 0
#define OFF_AL TILE_B
#define OFF_BH (2 * TILE_B)
#define OFF_BL (3 * TILE_B)

// ---------------- scratch ----------------
// A operands pre-split, interleaved per 4-element group: uint4 = (hi0,hi1,lo0,lo1)
__device__ float g_preact[SPLITK * BATCH * FEAT];              // 18.4 MB
__device__ __align__(256) uint4 g_xs[BATCH * INSZ / 4];        // 28.9 MB
__device__ __align__(256) uint4 g_ys[BATCH * FEAT_PAD / 4];    // 1.6 MB
__device__ float g_rownorm2[FEAT];

// ---------------- helpers ----------------
__device__ __forceinline__ uint32_t smem_u32(const void* p) {
    uint32_t a;
    asm("{ .reg .u64 t; cvta.to.shared.u64 t, %1; cvt.u32.u64 %0, t; }" : "=r"(a) : "l"(p));
    return a;
}
__device__ __forceinline__ float sigmoidf_(float z) { return 1.0f / (1.0f + __expf(-z)); }

// split f32 pair (x=k, y=k+1) into packed bf16x2 hi and lo words (k in low half)
__device__ __forceinline__ void split_pair(float x, float y, uint32_t& hw, uint32_t& lw) {
    uint32_t h;
    asm("cvt.rn.bf16x2.f32 %0, %1, %2;" : "=r"(h) : "f"(y), "f"(x));
    float hx = __uint_as_float(h << 16);
    float hy = __uint_as_float(h & 0xffff0000u);
    float lx = x - hx, ly = y - hy;
    asm("cvt.rn.bf16x2.f32 %0, %1, %2;" : "=r"(lw) : "f"(ly), "f"(lx));
    hw = h;
}

__device__ __forceinline__ void ldmx4(uint32_t r[4], uint32_t addr) {
    asm volatile("ldmatrix.sync.aligned.m8n8.x4.shared.b16 {%0,%1,%2,%3}, [%4];"
                 : "=r"(r[0]), "=r"(r[1]), "=r"(r[2]), "=r"(r[3]) : "r"(addr));
}
__device__ __forceinline__ void mma16816(float c[4], const uint32_t a[4], uint32_t b0, uint32_t b1) {
    asm volatile(
        "mma.sync.aligned.m16n8k16.row.col.f32.bf16.bf16.f32 "
        "{%0,%1,%2,%3}, {%4,%5,%6,%7}, {%8,%9}, {%0,%1,%2,%3};"
        : "+f"(c[0]), "+f"(c[1]), "+f"(c[2]), "+f"(c[3])
        : "r"(a[0]), "r"(a[1]), "r"(a[2]), "r"(a[3]), "r"(b0), "r"(b1));
}

// ---------------------------------------------------------------------------
// split-bf16 HMMA GEMM (R9 schedule): C[m,n] = sum_k A[m,k] * B[n,k]
//   A: pre-split interleaved uint4 groups [rows][ldaE/4], all K valid
//   B: f32 [N][ldb], K valid in [0, kvalidB)
//   mode 0: raw f32 partial -> C + z*BATCH*ldc ; fused W row-norms (y==0)
//   mode 1: sigmoid(acc + bias[n]) -> C
// ---------------------------------------------------------------------------
__global__ void __launch_bounds__(NTH, 2)
gemm_hmma(const uint4* __restrict__ As, const float* __restrict__ B,
          const float* __restrict__ bias, float* __restrict__ C,
          int N, int ldaE, int ldb, int kvalidB, int ldc,
          int kblk_per_split, int kblk_total, int mode)
{
    extern __shared__ char smem[];
    const uint32_t sb = smem_u32(smem);
    const int tid = threadIdx.x, wid = tid >> 5, lane = tid & 31;
    const int bm = blockIdx.y * BM;
    const int bn = blockIdx.x * BN;
    const int z  = blockIdx.z;
    const int kb0 = z * kblk_per_split;
    int nch = kblk_total - kb0;
    if (nch > kblk_per_split) nch = kblk_per_split;
    if (nch <= 0) return;

    const int wm = wid >> 2;        // 0..1 -> m offset wm*64
    const int wn = wid & 3;         // 0..3 -> n offset wn*32

    // loader: thread -> (row = tid>>2 (+64 per iter), quarter q = tid&3)
    const int lrow = tid >> 2;          // 0..63
    const int lq   = tid & 3;           // 4-element group along K (0..3)
    const bool do_rn = (mode == 0) && (blockIdx.y == 0);

    // hoisted row pointers (group-granular for A)
    const int lda4 = ldaE >> 2;
    const uint4* pA0 = As + (size_t)(bm + lrow) * lda4 + lq;
    const uint4* pA1 = As + (size_t)(bm + lrow + 64) * lda4 + lq;
    const int gn0 = bn + lrow, gn1 = bn + lrow + 64;
    const float* pB0 = B + (size_t)(gn0 < N ? gn0 : N - 1) * ldb + lq * 4;
    const float* pB1 = B + (size_t)(gn1 < N ? gn1 : N - 1) * ldb + lq * 4;
    const bool okn0 = gn0 < N, okn1 = gn1 < N;

    // hoisted smem addresses (both parities)
    char* const stP0 = smem + lrow * ROWB + lq * 8;
    char* const stP1 = stP0 + STAGE_B;
    const uint32_t aoff0 = sb + (uint32_t)((wm * 64 + (lane & 15)) * ROWB + (lane >> 4) * 16);
    const uint32_t aoff1 = aoff0 + STAGE_B;
    const uint32_t boff0 = sb + (uint32_t)((wn * 32 + (lane & 15)) * ROWB + (lane >> 4) * 16);
    const uint32_t boff1 = boff0 + STAGE_B;

    float acc[4][4][4];
    #pragma unroll
    for (int i = 0; i < 4; i++)
        #pragma unroll
        for (int j = 0; j < 4; j++)
            #pragma unroll
            for (int q = 0; q < 4; q++) acc[i][j][q] = 0.f;

    uint4  pa[2];            // A prefetch (interleaved hi/lo, one 16B LDG each)
    float4 pb[2];            // B prefetch (f32)
    float rn0 = 0.f, rn1 = 0.f;

// ---- register prefetch of chunk C ----
#define PREFETCH(C_) do {                                                     \
        const int kg = (kb0 + (C_)) * (BK / 4);                               \
        pa[0] = pA0[kg]; pa[1] = pA1[kg];                                     \
        const int kc = (kb0 + (C_)) * BK + lq * 4;                            \
        pb[0] = (okn0 && kc < kvalidB) ? *reinterpret_cast<const float4*>(pB0 + (kb0 + (C_)) * BK) \
                                       : make_float4(0.f, 0.f, 0.f, 0.f);     \
        pb[1] = (okn1 && kc < kvalidB) ? *reinterpret_cast<const float4*>(pB1 + (kb0 + (C_)) * BK) \
                                       : make_float4(0.f, 0.f, 0.f, 0.f);     \
    } while (0)

// ---- STS of prefetched regs into parity-P buffer ----
#define STS(STP) do {                                                         \
        char* st = (STP);                                                     \
        *reinterpret_cast<uint2*>(st + OFF_AH) = make_uint2(pa[0].x, pa[0].y);\
        *reinterpret_cast<uint2*>(st + OFF_AL) = make_uint2(pa[0].z, pa[0].w);\
        *reinterpret_cast<uint2*>(st + OFF_AH + 64 * ROWB) = make_uint2(pa[1].x, pa[1].y); \
        *reinterpret_cast<uint2*>(st + OFF_AL + 64 * ROWB) = make_uint2(pa[1].z, pa[1].w); \
        uint32_t hw0, lw0, hw1, lw1;                                          \
        split_pair(pb[0].x, pb[0].y, hw0, lw0);                               \
        split_pair(pb[0].z, pb[0].w, hw1, lw1);                               \
        *reinterpret_cast<uint2*>(st + OFF_BH) = make_uint2(hw0, hw1);        \
        *reinterpret_cast<uint2*>(st + OFF_BL) = make_uint2(lw0, lw1);        \
        split_pair(pb[1].x, pb[1].y, hw0, lw0);                               \
        split_pair(pb[1].z, pb[1].w, hw1, lw1);                               \
        *reinterpret_cast<uint2*>(st + OFF_BH + 64 * ROWB) = make_uint2(hw0, hw1); \
        *reinterpret_cast<uint2*>(st + OFF_BL + 64 * ROWB) = make_uint2(lw0, lw1); \
        if (do_rn) {                                                          \
            rn0 += pb[0].x * pb[0].x + pb[0].y * pb[0].y + pb[0].z * pb[0].z + pb[0].w * pb[0].w; \
            rn1 += pb[1].x * pb[1].x + pb[1].y * pb[1].y + pb[1].z * pb[1].z + pb[1].w * pb[1].w; \
        }                                                                     \
    } while (0)

// ---- compute one chunk from parity-P buffer (R9 fragment schedule) ----
#define COMPUTE(AOFF, BOFF) do {                                              \
        uint32_t bh[4][2], bl[4][2];                                          \
        _Pragma("unroll")                                                     \
        for (int bt = 0; bt < 2; bt++) {                                      \
            uint32_t t[4];                                                    \
            ldmx4(t, (BOFF) + OFF_BH + bt * 16 * ROWB);                       \
            bh[bt * 2 + 0][0] = t[0]; bh[bt * 2 + 0][1] = t[2];               \
            bh[bt * 2 + 1][0] = t[1]; bh[bt * 2 + 1][1] = t[3];               \
            ldmx4(t, (BOFF) + OFF_BL + bt * 16 * ROWB);                       \
            bl[bt * 2 + 0][0] = t[0]; bl[bt * 2 + 0][1] = t[2];               \
            bl[bt * 2 + 1][0] = t[1]; bl[bt * 2 + 1][1] = t[3];               \
        }                                                                     \
        _Pragma("unroll")                                                     \
        for (int mi = 0; mi < 4; mi++) {                                      \
            uint32_t ah[4], al[4];                                            \
            ldmx4(ah, (AOFF) + OFF_AH + mi * 16 * ROWB);                      \
            ldmx4(al, (AOFF) + OFF_AL + mi * 16 * ROWB);                      \
            _Pragma("unroll")                                                 \
            for (int ni = 0; ni < 4; ni++)                                    \
                mma16816(acc[mi][ni], ah, bh[ni][0], bh[ni][1]);              \
            _Pragma("unroll")                                                 \
            for (int ni = 0; ni < 4; ni++)                                    \
                mma16816(acc[mi][ni], al, bh[ni][0], bh[ni][1]);              \
            _Pragma("unroll")                                                 \
            for (int ni = 0; ni < 4; ni++)                                    \
                mma16816(acc[mi][ni], ah, bl[ni][0], bl[ni][1]);              \
        }                                                                     \
    } while (0)

// one R9-ordered step at compile-time parity P (compute P, STS into P^1)
#define STEP(CI, AOFF, BOFF, STNEXT) do {                                     \
        __syncthreads();                                                      \
        const bool pf = (CI) + 1 < nch;                                       \
        if (pf) PREFETCH((CI) + 1);                                           \
        COMPUTE(AOFF, BOFF);                                                  \
        if (pf) STS(STNEXT);                                                  \
    } while (0)

    // prologue: chunk 0 into buffer 0
    PREFETCH(0);
    STS(stP0);

    int ci = 0;
    for (; ci + 1 < nch; ci += 2) {
        STEP(ci,     aoff0, boff0, stP1);
        STEP(ci + 1, aoff1, boff1, stP0);
    }
    if (ci < nch) STEP(ci, aoff0, boff0, stP1);

#undef STEP
#undef COMPUTE
#undef STS
#undef PREFETCH

    // ---- fused row-norm output (encoder, bm slice 0 only) ----
    if (do_rn) {
        rn0 += __shfl_xor_sync(0xffffffffu, rn0, 1);
        rn0 += __shfl_xor_sync(0xffffffffu, rn0, 2);
        rn1 += __shfl_xor_sync(0xffffffffu, rn1, 1);
        rn1 += __shfl_xor_sync(0xffffffffu, rn1, 2);
        if (lq == 0) {
            if (okn0) atomicAdd(&g_rownorm2[gn0], rn0);
            if (okn1) atomicAdd(&g_rownorm2[gn1], rn1);
        }
    }

    // ---- epilogue (identical to R9) ----
    const int er = lane >> 2, ec = (lane & 3) * 2;
    #pragma unroll
    for (int mi = 0; mi < 4; mi++) {
        #pragma unroll
        for (int ni = 0; ni < 4; ni++) {
            int m0 = bm + wm * 64 + mi * 16 + er;
            int n0 = bn + wn * 32 + ni * 8 + ec;
            if (mode == 0) {
                float* Cz = C + (size_t)z * BATCH * ldc;
                if (n0 + 1 < N) {
                    *reinterpret_cast<float2*>(Cz + (size_t)m0 * ldc + n0) =
                        make_float2(acc[mi][ni][0], acc[mi][ni][1]);
                    *reinterpret_cast<float2*>(Cz + (size_t)(m0 + 8) * ldc + n0) =
                        make_float2(acc[mi][ni][2], acc[mi][ni][3]);
                } else if (n0 < N) {
                    Cz[(size_t)m0 * ldc + n0] = acc[mi][ni][0];
                    Cz[(size_t)(m0 + 8) * ldc + n0] = acc[mi][ni][2];
                }
            } else {
                if (n0 + 1 < N) {
                    float b0 = bias[n0], b1 = bias[n0 + 1];
                    *reinterpret_cast<float2*>(C + (size_t)m0 * ldc + n0) =
                        make_float2(sigmoidf_(acc[mi][ni][0] + b0), sigmoidf_(acc[mi][ni][1] + b1));
                    *reinterpret_cast<float2*>(C + (size_t)(m0 + 8) * ldc + n0) =
                        make_float2(sigmoidf_(acc[mi][ni][2] + b0), sigmoidf_(acc[mi][ni][3] + b1));
                } else if (n0 < N) {
                    float b0 = bias[n0];
                    C[(size_t)m0 * ldc + n0] = sigmoidf_(acc[mi][ni][0] + b0);
                    C[(size_t)(m0 + 8) * ldc + n0] = sigmoidf_(acc[mi][ni][2] + b0);
                }
            }
        }
    }
}

// ---------------------------------------------------------------------------
// x f32 -> interleaved split groups (hi0,hi1,lo0,lo1); zero rownorm + jac
// ---------------------------------------------------------------------------
__global__ void convert_x(const float4* __restrict__ x4, float* __restrict__ jac_init) {
    int i = blockIdx.x * 256 + threadIdx.x;
    if (i < BATCH * INSZ / 4) {
        float4 v = x4[i];
        uint32_t h0, l0, h1, l1;
        split_pair(v.x, v.y, h0, l0);
        split_pair(v.z, v.w, h1, l1);
        g_xs[i] = make_uint4(h0, h1, l0, l1);
    }
    if (i < FEAT) g_rownorm2[i] = 0.f;
    if (i == 0) *jac_init = 0.f;
}

// ---------------------------------------------------------------------------
// encoder epilogue: sum split-K partials + bias -> sigmoid -> y_enc split
// (interleaved groups), accumulate jac_reg
// ---------------------------------------------------------------------------
__global__ void enc_epilogue(const float* __restrict__ b_enc, float* __restrict__ jac_out) {
    int idx = blockIdx.x * blockDim.x + threadIdx.x;   // one 4-element group
    float part = 0.f;
    if (idx < BATCH * FEAT_PAD / 4) {
        int m = idx / (FEAT_PAD / 4), g = idx % (FEAT_PAD / 4);
        float y[4];
        #pragma unroll
        for (int p = 0; p < 4; p++) {
            int f = g * 4 + p;
            if (f < FEAT) {
                float zsum = b_enc[f];
                int base = m * FEAT + f;
                #pragma unroll
                for (int s = 0; s < SPLITK; s++)
                    zsum += g_preact[(size_t)s * BATCH * FEAT + base];
                y[p] = sigmoidf_(zsum);
                float sd = y[p] * (1.f - y[p]);
                part += sd * sd * g_rownorm2[f];
            } else {
                y[p] = 0.f;
            }
        }
        uint32_t h0, l0, h1, l1;
        split_pair(y[0], y[1], h0, l0);
        split_pair(y[2], y[3], h1, l1);
        g_ys[idx] = make_uint4(h0, h1, l0, l1);
    }
    #pragma unroll
    for (int o = 16; o > 0; o >>= 1) part += __shfl_down_sync(0xffffffffu, part, o);
    __shared__ float wsum[8];
    int lane = threadIdx.x & 31, wid = threadIdx.x >> 5;
    if (lane == 0) wsum[wid] = part;
    __syncthreads();
    if (wid == 0) {
        float v = (lane < 8) ? wsum[lane] : 0.f;
        #pragma unroll
        for (int o = 4; o > 0; o >>= 1) v += __shfl_down_sync(0xffffffffu, v, o);
        if (lane == 0) atomicAdd(jac_out, v);
    }
}

// ---------------------------------------------------------------------------
extern "C" void kernel_launch(void* const* d_in, const int* in_sizes, int n_in,
                              void* d_out, int out_size) {
    const float* x     = (const float*)d_in[0];
    const float* W_enc = (const float*)d_in[1];
    const float* b_enc = (const float*)d_in[2];
    const float* W_dec = (const float*)d_in[3];
    const float* b_dec = (const float*)d_in[4];
    float* out = (float*)d_out;
    float* jac = out + (out_size - 1);

    float* preact;
    uint4 *xs, *ys;
    cudaGetSymbolAddress((void**)&preact, g_preact);
    cudaGetSymbolAddress((void**)&xs, g_xs);
    cudaGetSymbolAddress((void**)&ys, g_ys);

    cudaFuncSetAttribute(gemm_hmma, cudaFuncAttributeMaxDynamicSharedMemorySize, SMEM_TOTAL);

    // 1) x -> interleaved bf16 hi/lo split; zero rownorm + jac
    convert_x<<<(BATCH * INSZ / 4 + 255) / 256, 256>>>((const float4*)x, jac);

    // 2) encoder GEMM (fused W_enc row norms): split-K=12 -> 288 CTAs
    {
        dim3 grid((FEAT + BN - 1) / BN, BATCH / BM, SPLITK);   // (12, 2, 12)
        gemm_hmma<<<grid, NTH, SMEM_TOTAL>>>(
            xs, W_enc, nullptr, preact,
            FEAT, INSZ, INSZ, INSZ, FEAT,
            ENC_KBLK_PER_SPLIT, ENC_KBLK_TOTAL, 0);
    }

    // 3) bias + sigmoid -> y_enc split; jacobian reduction
    enc_epilogue<<<(BATCH * FEAT_PAD / 4 + 255) / 256, 256>>>(b_enc, jac);

    // 4) decoder GEMM with fused bias+sigmoid
    {
        dim3 grid((INSZ + BN - 1) / BN, BATCH / BM, 1);        // (221, 2, 1)
        gemm_hmma<<<grid, NTH, SMEM_TOTAL>>>(
            ys, W_dec, b_dec, out,
            INSZ, FEAT_PAD, FEAT, FEAT, INSZ,
            DEC_KBLK, DEC_KBLK, 1);
    }
}

// round 16
// speedup vs baseline: 1.1072x; 1.1072x over previous
#include <cuda_runtime.h>
#include <cuda_bf16.h>
#include <cstdint>

// ---------------- problem constants ----------------
#define BATCH    256
#define FEAT     1500
#define FEAT_PAD 1504          // 94 * 16, padded K for decoder (zero-filled)
#define INSZ     28224
#define SPLITK   12
#define ENC_KBLK_TOTAL 1764    // 28224 / 16
#define ENC_KBLK_PER_SPLIT 147 // 12 * 147 = 1764 exactly
#define DEC_KBLK 94            // 1504 / 16

// ---------------- GEMM tile config -----------------
#define BM 128
#define BN 128
#define BK 16                  // K elements per chunk
#define NTH 256                // 8 warps: 2 (M) x 4 (N), warp tile 64x32

// smem: 4 tiles per stage (Ah, Al, Bh, Bl), each 128 rows x 16 bf16, row padded
// to 48B -> ldmatrix 8-row groups hit 8 distinct 16B segments (conflict-free)
#define ROWB   48
#define TILE_B (128 * ROWB)    // 6144
#define STAGE_B (4 * TILE_B)   // 24576
#define SMEM_TOTAL (2 * STAGE_B)  // 49152 -> 2 CTAs = 96KB/SM

#define OFF_AH 0
#define OFF_AL TILE_B
#define OFF_BH (2 * TILE_B)
#define OFF_BL (3 * TILE_B)

// ---------------- scratch ----------------
__device__ float g_preact[SPLITK * BATCH * FEAT];      // 18.4 MB
__device__ float g_yenc[BATCH * FEAT_PAD];             // zero-padded cols
__device__ float g_rownorm2[FEAT];

// ---------------- helpers ----------------
__device__ __forceinline__ uint32_t smem_u32(const void* p) {
    uint32_t a;
    asm("{ .reg .u64 t; cvta.to.shared.u64 t, %1; cvt.u32.u64 %0, t; }" : "=r"(a) : "l"(p));
    return a;
}
__device__ __forceinline__ float sigmoidf_(float z) { return 1.0f / (1.0f + __expf(-z)); }

// split f32 pair (x=k, y=k+1) into packed bf16x2 hi and lo words (k in low half)
__device__ __forceinline__ void split_pair(float x, float y, uint32_t& hw, uint32_t& lw) {
    uint32_t h;
    asm("cvt.rn.bf16x2.f32 %0, %1, %2;" : "=r"(h) : "f"(y), "f"(x));
    float hx = __uint_as_float(h << 16);
    float hy = __uint_as_float(h & 0xffff0000u);
    float lx = x - hx, ly = y - hy;
    asm("cvt.rn.bf16x2.f32 %0, %1, %2;" : "=r"(lw) : "f"(ly), "f"(lx));
    hw = h;
}

__device__ __forceinline__ void ldmx4(uint32_t r[4], uint32_t addr) {
    asm volatile("ldmatrix.sync.aligned.m8n8.x4.shared.b16 {%0,%1,%2,%3}, [%4];"
                 : "=r"(r[0]), "=r"(r[1]), "=r"(r[2]), "=r"(r[3]) : "r"(addr));
}
__device__ __forceinline__ void mma16816(float c[4], const uint32_t a[4], uint32_t b0, uint32_t b1) {
    asm volatile(
        "mma.sync.aligned.m16n8k16.row.col.f32.bf16.bf16.f32 "
        "{%0,%1,%2,%3}, {%4,%5,%6,%7}, {%8,%9}, {%0,%1,%2,%3};"
        : "+f"(c[0]), "+f"(c[1]), "+f"(c[2]), "+f"(c[3])
        : "r"(a[0]), "r"(a[1]), "r"(a[2]), "r"(a[3]), "r"(b0), "r"(b1));
}

// ---------------------------------------------------------------------------
// split-bf16 HMMA GEMM (R9 schedule, byte-identical core):
//   C[m,n] = sum_k A[m,k] * B[n,k]
//   MODE 0: raw f32 partial -> C + z*BATCH*ldc ; fused W row-norms (y==0)
//   MODE 1: sigmoid(acc + bias[n]) -> C
// ---------------------------------------------------------------------------
template <int MODE>
__global__ void __launch_bounds__(NTH, 2)
gemm_hmma(const float* __restrict__ A, const float* __restrict__ B,
          const float* __restrict__ bias, float* __restrict__ C,
          int N, int lda, int ldb, int kvalidB, int ldc,
          int kblk_per_split, int kblk_total)
{
    extern __shared__ char smem[];
    const uint32_t sb = smem_u32(smem);
    const int tid = threadIdx.x, wid = tid >> 5, lane = tid & 31;
    const int bm = blockIdx.y * BM;
    const int bn = blockIdx.x * BN;
    const int z  = blockIdx.z;
    const int kb0 = z * kblk_per_split;
    int nch = kblk_total - kb0;
    if (nch > kblk_per_split) nch = kblk_per_split;
    if (nch <= 0) return;

    const int wm = wid >> 2;        // 0..1 -> m offset wm*64
    const int wn = wid & 3;         // 0..3 -> n offset wn*32

    // loader: thread -> (row = tid>>2 (+64 per iter), quarter q = tid&3)
    const int lrow = tid >> 2;          // 0..63
    const int lq   = tid & 3;           // float4 index along K (0..3)
    const bool do_rn = (MODE == 0) && (blockIdx.y == 0);

    float acc[4][4][4];
    #pragma unroll
    for (int i = 0; i < 4; i++)
        #pragma unroll
        for (int j = 0; j < 4; j++)
            #pragma unroll
            for (int q = 0; q < 4; q++) acc[i][j][q] = 0.f;

    float4 pa[2], pb[2];
    float rn0 = 0.f, rn1 = 0.f;   // fused row-norm partials (rows bn+lrow, bn+lrow+64)

    // ---- prefetch chunk 0 ----
    {
        const int kc = kb0 * BK + lq * 4;
        #pragma unroll
        for (int it = 0; it < 2; it++) {
            int row = lrow + it * 64;
            pa[it] = *reinterpret_cast<const float4*>(A + (size_t)(bm + row) * lda + kc);
            int gn = bn + row;
            float4 v = make_float4(0.f, 0.f, 0.f, 0.f);
            if (gn < N && kc < kvalidB)
                v = *reinterpret_cast<const float4*>(B + (size_t)gn * ldb + kc);
            pb[it] = v;
        }
    }
    // ---- STS chunk 0 into buf 0 ----
    {
        char* st = smem;
        #pragma unroll
        for (int it = 0; it < 2; it++) {
            int row = lrow + it * 64;
            uint32_t off = (uint32_t)(row * ROWB + lq * 8);
            uint32_t hw0, lw0, hw1, lw1;
            split_pair(pa[it].x, pa[it].y, hw0, lw0);
            split_pair(pa[it].z, pa[it].w, hw1, lw1);
            *reinterpret_cast<uint2*>(st + OFF_AH + off) = make_uint2(hw0, hw1);
            *reinterpret_cast<uint2*>(st + OFF_AL + off) = make_uint2(lw0, lw1);
            split_pair(pb[it].x, pb[it].y, hw0, lw0);
            split_pair(pb[it].z, pb[it].w, hw1, lw1);
            *reinterpret_cast<uint2*>(st + OFF_BH + off) = make_uint2(hw0, hw1);
            *reinterpret_cast<uint2*>(st + OFF_BL + off) = make_uint2(lw0, lw1);
        }
        if (do_rn) {
            rn0 += pb[0].x * pb[0].x + pb[0].y * pb[0].y + pb[0].z * pb[0].z + pb[0].w * pb[0].w;
            rn1 += pb[1].x * pb[1].x + pb[1].y * pb[1].y + pb[1].z * pb[1].z + pb[1].w * pb[1].w;
        }
    }

    const int lr = lane & 15;          // row within 16-row tile
    const int lc = lane >> 4;          // 0/1 -> +16B (k8..k15 half)

    for (int ci = 0; ci < nch; ci++) {
        __syncthreads();   // STS(ci) visible; compute(ci-1) done

        // prefetch chunk ci+1 (held in regs during compute)
        if (ci + 1 < nch) {
            const int kc = (kb0 + ci + 1) * BK + lq * 4;
            #pragma unroll
            for (int it = 0; it < 2; it++) {
                int row = lrow + it * 64;
                pa[it] = *reinterpret_cast<const float4*>(A + (size_t)(bm + row) * lda + kc);
                int gn = bn + row;
                float4 v = make_float4(0.f, 0.f, 0.f, 0.f);
                if (gn < N && kc < kvalidB)
                    v = *reinterpret_cast<const float4*>(B + (size_t)gn * ldb + kc);
                pb[it] = v;
            }
        }

        // ---- compute chunk ci from buf ci&1 (identical to R9) ----
        const uint32_t stg = sb + (uint32_t)((ci & 1) * STAGE_B);
        {
            uint32_t bh[4][2], bl[4][2];
            const uint32_t b_off = stg + (uint32_t)((wn * 32 + lr) * ROWB + lc * 16);
            #pragma unroll
            for (int bt = 0; bt < 2; bt++) {
                uint32_t t[4];
                ldmx4(t, b_off + OFF_BH + bt * 16 * ROWB);
                bh[bt * 2 + 0][0] = t[0]; bh[bt * 2 + 0][1] = t[2];
                bh[bt * 2 + 1][0] = t[1]; bh[bt * 2 + 1][1] = t[3];
                ldmx4(t, b_off + OFF_BL + bt * 16 * ROWB);
                bl[bt * 2 + 0][0] = t[0]; bl[bt * 2 + 0][1] = t[2];
                bl[bt * 2 + 1][0] = t[1]; bl[bt * 2 + 1][1] = t[3];
            }
            const uint32_t a_off = stg + (uint32_t)((wm * 64 + lr) * ROWB + lc * 16);
            #pragma unroll
            for (int mi = 0; mi < 4; mi++) {
                uint32_t ah[4], al[4];
                ldmx4(ah, a_off + OFF_AH + mi * 16 * ROWB);
                ldmx4(al, a_off + OFF_AL + mi * 16 * ROWB);
                #pragma unroll
                for (int ni = 0; ni < 4; ni++)
                    mma16816(acc[mi][ni], ah, bh[ni][0], bh[ni][1]);
                #pragma unroll
                for (int ni = 0; ni < 4; ni++)
                    mma16816(acc[mi][ni], al, bh[ni][0], bh[ni][1]);
                #pragma unroll
                for (int ni = 0; ni < 4; ni++)
                    mma16816(acc[mi][ni], ah, bl[ni][0], bl[ni][1]);
            }
        }

        // ---- STS chunk ci+1 into other buffer (R9 position) ----
        if (ci + 1 < nch) {
            char* st = smem + ((ci + 1) & 1) * STAGE_B;
            #pragma unroll
            for (int it = 0; it < 2; it++) {
                int row = lrow + it * 64;
                uint32_t off = (uint32_t)(row * ROWB + lq * 8);
                uint32_t hw0, lw0, hw1, lw1;
                split_pair(pa[it].x, pa[it].y, hw0, lw0);
                split_pair(pa[it].z, pa[it].w, hw1, lw1);
                *reinterpret_cast<uint2*>(st + OFF_AH + off) = make_uint2(hw0, hw1);
                *reinterpret_cast<uint2*>(st + OFF_AL + off) = make_uint2(lw0, lw1);
                split_pair(pb[it].x, pb[it].y, hw0, lw0);
                split_pair(pb[it].z, pb[it].w, hw1, lw1);
                *reinterpret_cast<uint2*>(st + OFF_BH + off) = make_uint2(hw0, hw1);
                *reinterpret_cast<uint2*>(st + OFF_BL + off) = make_uint2(lw0, lw1);
            }
            if (do_rn) {
                rn0 += pb[0].x * pb[0].x + pb[0].y * pb[0].y + pb[0].z * pb[0].z + pb[0].w * pb[0].w;
                rn1 += pb[1].x * pb[1].x + pb[1].y * pb[1].y + pb[1].z * pb[1].z + pb[1].w * pb[1].w;
            }
        }
    }

    // ---- fused row-norm output (encoder, bm slice 0 only) ----
    if (do_rn) {
        rn0 += __shfl_xor_sync(0xffffffffu, rn0, 1);
        rn0 += __shfl_xor_sync(0xffffffffu, rn0, 2);
        rn1 += __shfl_xor_sync(0xffffffffu, rn1, 1);
        rn1 += __shfl_xor_sync(0xffffffffu, rn1, 2);
        if (lq == 0) {
            int r0 = bn + lrow, r1 = bn + lrow + 64;
            if (r0 < N) atomicAdd(&g_rownorm2[r0], rn0);
            if (r1 < N) atomicAdd(&g_rownorm2[r1], rn1);
        }
    }

    // ---- epilogue (identical to R9, compile-time mode) ----
    const int er = lane >> 2, ec = (lane & 3) * 2;
    #pragma unroll
    for (int mi = 0; mi < 4; mi++) {
        #pragma unroll
        for (int ni = 0; ni < 4; ni++) {
            int m0 = bm + wm * 64 + mi * 16 + er;
            int n0 = bn + wn * 32 + ni * 8 + ec;
            if (MODE == 0) {
                float* Cz = C + (size_t)z * BATCH * ldc;
                if (n0 + 1 < N) {
                    *reinterpret_cast<float2*>(Cz + (size_t)m0 * ldc + n0) =
                        make_float2(acc[mi][ni][0], acc[mi][ni][1]);
                    *reinterpret_cast<float2*>(Cz + (size_t)(m0 + 8) * ldc + n0) =
                        make_float2(acc[mi][ni][2], acc[mi][ni][3]);
                } else if (n0 < N) {
                    Cz[(size_t)m0 * ldc + n0] = acc[mi][ni][0];
                    Cz[(size_t)(m0 + 8) * ldc + n0] = acc[mi][ni][2];
                }
            } else {
                if (n0 + 1 < N) {
                    float b0 = bias[n0], b1 = bias[n0 + 1];
                    *reinterpret_cast<float2*>(C + (size_t)m0 * ldc + n0) =
                        make_float2(sigmoidf_(acc[mi][ni][0] + b0), sigmoidf_(acc[mi][ni][1] + b1));
                    *reinterpret_cast<float2*>(C + (size_t)(m0 + 8) * ldc + n0) =
                        make_float2(sigmoidf_(acc[mi][ni][2] + b0), sigmoidf_(acc[mi][ni][3] + b1));
                } else if (n0 < N) {
                    float b0 = bias[n0];
                    C[(size_t)m0 * ldc + n0] = sigmoidf_(acc[mi][ni][0] + b0);
                    C[(size_t)(m0 + 8) * ldc + n0] = sigmoidf_(acc[mi][ni][2] + b0);
                }
            }
        }
    }
}

// ---------------------------------------------------------------------------
// zero row-norm accumulators + jac (replaces the 27us rownorm kernel)
// ---------------------------------------------------------------------------
__global__ void init_misc(float* __restrict__ jac_init) {
    int i = blockIdx.x * 256 + threadIdx.x;
    if (i < FEAT) g_rownorm2[i] = 0.f;
    if (i == 0) *jac_init = 0.f;
}

// ---------------------------------------------------------------------------
// encoder epilogue: sum split-K partials + bias -> sigmoid -> y_enc (padded),
// accumulate jac_reg (row norms came from the fused encoder GEMM)
// ---------------------------------------------------------------------------
__global__ void enc_epilogue(const float* __restrict__ b_enc, float* __restrict__ jac_out) {
    int idx = blockIdx.x * blockDim.x + threadIdx.x;
    float part = 0.f;
    if (idx < BATCH * FEAT_PAD) {
        int m = idx / FEAT_PAD, f = idx % FEAT_PAD;
        if (f < FEAT) {
            float zsum = b_enc[f];
            int base = m * FEAT + f;
            #pragma unroll
            for (int s = 0; s < SPLITK; s++)
                zsum += g_preact[(size_t)s * BATCH * FEAT + base];
            float y = sigmoidf_(zsum);
            g_yenc[idx] = y;
            float sd = y * (1.f - y);
            part = sd * sd * g_rownorm2[f];
        } else {
            g_yenc[idx] = 0.f;  // zero pad for decoder K
        }
    }
    #pragma unroll
    for (int o = 16; o > 0; o >>= 1) part += __shfl_down_sync(0xffffffffu, part, o);
    __shared__ float wsum[8];
    int lane = threadIdx.x & 31, wid = threadIdx.x >> 5;
    if (lane == 0) wsum[wid] = part;
    __syncthreads();
    if (wid == 0) {
        float v = (lane < 8) ? wsum[lane] : 0.f;
        #pragma unroll
        for (int o = 4; o > 0; o >>= 1) v += __shfl_down_sync(0xffffffffu, v, o);
        if (lane == 0) atomicAdd(jac_out, v);
    }
}

// ---------------------------------------------------------------------------
extern "C" void kernel_launch(void* const* d_in, const int* in_sizes, int n_in,
                              void* d_out, int out_size) {
    const float* x     = (const float*)d_in[0];
    const float* W_enc = (const float*)d_in[1];
    const float* b_enc = (const float*)d_in[2];
    const float* W_dec = (const float*)d_in[3];
    const float* b_dec = (const float*)d_in[4];
    float* out = (float*)d_out;
    float* jac = out + (out_size - 1);

    float *preact, *yenc;
    cudaGetSymbolAddress((void**)&preact, g_preact);
    cudaGetSymbolAddress((void**)&yenc,  g_yenc);

    cudaFuncSetAttribute(gemm_hmma<0>, cudaFuncAttributeMaxDynamicSharedMemorySize, SMEM_TOTAL);
    cudaFuncSetAttribute(gemm_hmma<1>, cudaFuncAttributeMaxDynamicSharedMemorySize, SMEM_TOTAL);

    // 1) zero rownorm accumulators + jac
    init_misc<<<(FEAT + 255) / 256, 256>>>(jac);

    // 2) encoder GEMM (fused W_enc row norms): split-K=12 -> 288 CTAs
    {
        dim3 grid((FEAT + BN - 1) / BN, BATCH / BM, SPLITK);   // (12, 2, 12)
        gemm_hmma<0><<<grid, NTH, SMEM_TOTAL>>>(
            x, W_enc, nullptr, preact,
            FEAT, INSZ, INSZ, INSZ, FEAT,
            ENC_KBLK_PER_SPLIT, ENC_KBLK_TOTAL);
    }

    // 3) bias + sigmoid -> y_enc (padded); jacobian reduction
    enc_epilogue<<<(BATCH * FEAT_PAD + 255) / 256, 256>>>(b_enc, jac);

    // 4) decoder GEMM with fused bias+sigmoid
    {
        dim3 grid((INSZ + BN - 1) / BN, BATCH / BM, 1);        // (221, 2, 1)
        gemm_hmma<1><<<grid, NTH, SMEM_TOTAL>>>(
            yenc, W_dec, b_dec, out,
            INSZ, FEAT_PAD, FEAT, FEAT, INSZ,
            DEC_KBLK, DEC_KBLK);
    }
}

// round 17
// speedup vs baseline: 1.1177x; 1.0094x over previous
#include <cuda_runtime.h>
#include <cuda_bf16.h>
#include <cstdint>

// ---------------- problem constants ----------------
#define BATCH    256
#define FEAT     1500
#define FEAT_PAD 1504          // 94 * 16, padded K for decoder (zero-filled)
#define INSZ     28224
#define SPLITK   12
#define ENC_KBLK_TOTAL 1764    // 28224 / 16
#define ENC_KBLK_PER_SPLIT 147 // 12 * 147 = 1764 exactly
#define DEC_KBLK_TOTAL 94      // 1504 / 16
#define DEC_SPLITK 2
#define DEC_KBLK_PER_SPLIT 47  // 2 * 47 = 94

// ---------------- GEMM tile config -----------------
#define BM 128
#define BN 128
#define BK 16                  // K elements per chunk
#define NTH 256                // 8 warps: 2 (M) x 4 (N), warp tile 64x32

// smem: 4 tiles per stage (Ah, Al, Bh, Bl), each 128 rows x 16 bf16, row padded
// to 48B -> ldmatrix 8-row groups hit 8 distinct 16B segments (conflict-free)
#define ROWB   48
#define TILE_B (128 * ROWB)    // 6144
#define STAGE_B (4 * TILE_B)   // 24576
#define SMEM_TOTAL (2 * STAGE_B)  // 49152 -> 2 CTAs = 96KB/SM

#define OFF_AH 0
#define OFF_AL TILE_B
#define OFF_BH (2 * TILE_B)
#define OFF_BL (3 * TILE_B)

// ---------------- scratch ----------------
__device__ float g_preact[SPLITK * BATCH * FEAT];        // 18.4 MB
__device__ float g_yenc[BATCH * FEAT_PAD];               // zero-padded cols
__device__ float g_dpart[DEC_SPLITK * BATCH * INSZ];     // 57.8 MB decoder partials
__device__ float g_rownorm2[FEAT];

// ---------------- helpers ----------------
__device__ __forceinline__ uint32_t smem_u32(const void* p) {
    uint32_t a;
    asm("{ .reg .u64 t; cvta.to.shared.u64 t, %1; cvt.u32.u64 %0, t; }" : "=r"(a) : "l"(p));
    return a;
}
__device__ __forceinline__ float sigmoidf_(float z) { return 1.0f / (1.0f + __expf(-z)); }

// split f32 pair (x=k, y=k+1) into packed bf16x2 hi and lo words (k in low half)
__device__ __forceinline__ void split_pair(float x, float y, uint32_t& hw, uint32_t& lw) {
    uint32_t h;
    asm("cvt.rn.bf16x2.f32 %0, %1, %2;" : "=r"(h) : "f"(y), "f"(x));
    float hx = __uint_as_float(h << 16);
    float hy = __uint_as_float(h & 0xffff0000u);
    float lx = x - hx, ly = y - hy;
    asm("cvt.rn.bf16x2.f32 %0, %1, %2;" : "=r"(lw) : "f"(ly), "f"(lx));
    hw = h;
}

__device__ __forceinline__ void ldmx4(uint32_t r[4], uint32_t addr) {
    asm volatile("ldmatrix.sync.aligned.m8n8.x4.shared.b16 {%0,%1,%2,%3}, [%4];"
                 : "=r"(r[0]), "=r"(r[1]), "=r"(r[2]), "=r"(r[3]) : "r"(addr));
}
__device__ __forceinline__ void mma16816(float c[4], const uint32_t a[4], uint32_t b0, uint32_t b1) {
    asm volatile(
        "mma.sync.aligned.m16n8k16.row.col.f32.bf16.bf16.f32 "
        "{%0,%1,%2,%3}, {%4,%5,%6,%7}, {%8,%9}, {%0,%1,%2,%3};"
        : "+f"(c[0]), "+f"(c[1]), "+f"(c[2]), "+f"(c[3])
        : "r"(a[0]), "r"(a[1]), "r"(a[2]), "r"(a[3]), "r"(b0), "r"(b1));
}

// ---------------------------------------------------------------------------
// split-bf16 HMMA GEMM (R9 schedule, byte-identical core):
//   C[m,n] = sum_k A[m,k] * B[n,k]
//   MODE 0: raw f32 partial -> C + z*BATCH*ldc ; fused W row-norms (y==0)
//   MODE 2: raw f32 partial -> C + z*BATCH*ldc ; no row-norms
// ---------------------------------------------------------------------------
template <int MODE>
__global__ void __launch_bounds__(NTH, 2)
gemm_hmma(const float* __restrict__ A, const float* __restrict__ B,
          const float* __restrict__ bias, float* __restrict__ C,
          int N, int lda, int ldb, int kvalidB, int ldc,
          int kblk_per_split, int kblk_total)
{
    extern __shared__ char smem[];
    const uint32_t sb = smem_u32(smem);
    const int tid = threadIdx.x, wid = tid >> 5, lane = tid & 31;
    const int bm = blockIdx.y * BM;
    const int bn = blockIdx.x * BN;
    const int z  = blockIdx.z;
    const int kb0 = z * kblk_per_split;
    int nch = kblk_total - kb0;
    if (nch > kblk_per_split) nch = kblk_per_split;
    if (nch <= 0) return;

    const int wm = wid >> 2;        // 0..1 -> m offset wm*64
    const int wn = wid & 3;         // 0..3 -> n offset wn*32

    // loader: thread -> (row = tid>>2 (+64 per iter), quarter q = tid&3)
    const int lrow = tid >> 2;          // 0..63
    const int lq   = tid & 3;           // float4 index along K (0..3)
    const bool do_rn = (MODE == 0) && (blockIdx.y == 0);

    float acc[4][4][4];
    #pragma unroll
    for (int i = 0; i < 4; i++)
        #pragma unroll
        for (int j = 0; j < 4; j++)
            #pragma unroll
            for (int q = 0; q < 4; q++) acc[i][j][q] = 0.f;

    float4 pa[2], pb[2];
    float rn0 = 0.f, rn1 = 0.f;   // fused row-norm partials (rows bn+lrow, bn+lrow+64)

    // ---- prefetch chunk 0 ----
    {
        const int kc = kb0 * BK + lq * 4;
        #pragma unroll
        for (int it = 0; it < 2; it++) {
            int row = lrow + it * 64;
            pa[it] = *reinterpret_cast<const float4*>(A + (size_t)(bm + row) * lda + kc);
            int gn = bn + row;
            float4 v = make_float4(0.f, 0.f, 0.f, 0.f);
            if (gn < N && kc < kvalidB)
                v = *reinterpret_cast<const float4*>(B + (size_t)gn * ldb + kc);
            pb[it] = v;
        }
    }
    // ---- STS chunk 0 into buf 0 ----
    {
        char* st = smem;
        #pragma unroll
        for (int it = 0; it < 2; it++) {
            int row = lrow + it * 64;
            uint32_t off = (uint32_t)(row * ROWB + lq * 8);
            uint32_t hw0, lw0, hw1, lw1;
            split_pair(pa[it].x, pa[it].y, hw0, lw0);
            split_pair(pa[it].z, pa[it].w, hw1, lw1);
            *reinterpret_cast<uint2*>(st + OFF_AH + off) = make_uint2(hw0, hw1);
            *reinterpret_cast<uint2*>(st + OFF_AL + off) = make_uint2(lw0, lw1);
            split_pair(pb[it].x, pb[it].y, hw0, lw0);
            split_pair(pb[it].z, pb[it].w, hw1, lw1);
            *reinterpret_cast<uint2*>(st + OFF_BH + off) = make_uint2(hw0, hw1);
            *reinterpret_cast<uint2*>(st + OFF_BL + off) = make_uint2(lw0, lw1);
        }
        if (do_rn) {
            rn0 += pb[0].x * pb[0].x + pb[0].y * pb[0].y + pb[0].z * pb[0].z + pb[0].w * pb[0].w;
            rn1 += pb[1].x * pb[1].x + pb[1].y * pb[1].y + pb[1].z * pb[1].z + pb[1].w * pb[1].w;
        }
    }

    const int lr = lane & 15;          // row within 16-row tile
    const int lc = lane >> 4;          // 0/1 -> +16B (k8..k15 half)

    for (int ci = 0; ci < nch; ci++) {
        __syncthreads();   // STS(ci) visible; compute(ci-1) done

        // prefetch chunk ci+1 (held in regs during compute)
        if (ci + 1 < nch) {
            const int kc = (kb0 + ci + 1) * BK + lq * 4;
            #pragma unroll
            for (int it = 0; it < 2; it++) {
                int row = lrow + it * 64;
                pa[it] = *reinterpret_cast<const float4*>(A + (size_t)(bm + row) * lda + kc);
                int gn = bn + row;
                float4 v = make_float4(0.f, 0.f, 0.f, 0.f);
                if (gn < N && kc < kvalidB)
                    v = *reinterpret_cast<const float4*>(B + (size_t)gn * ldb + kc);
                pb[it] = v;
            }
        }

        // ---- compute chunk ci from buf ci&1 (identical to R9) ----
        const uint32_t stg = sb + (uint32_t)((ci & 1) * STAGE_B);
        {
            uint32_t bh[4][2], bl[4][2];
            const uint32_t b_off = stg + (uint32_t)((wn * 32 + lr) * ROWB + lc * 16);
            #pragma unroll
            for (int bt = 0; bt < 2; bt++) {
                uint32_t t[4];
                ldmx4(t, b_off + OFF_BH + bt * 16 * ROWB);
                bh[bt * 2 + 0][0] = t[0]; bh[bt * 2 + 0][1] = t[2];
                bh[bt * 2 + 1][0] = t[1]; bh[bt * 2 + 1][1] = t[3];
                ldmx4(t, b_off + OFF_BL + bt * 16 * ROWB);
                bl[bt * 2 + 0][0] = t[0]; bl[bt * 2 + 0][1] = t[2];
                bl[bt * 2 + 1][0] = t[1]; bl[bt * 2 + 1][1] = t[3];
            }
            const uint32_t a_off = stg + (uint32_t)((wm * 64 + lr) * ROWB + lc * 16);
            #pragma unroll
            for (int mi = 0; mi < 4; mi++) {
                uint32_t ah[4], al[4];
                ldmx4(ah, a_off + OFF_AH + mi * 16 * ROWB);
                ldmx4(al, a_off + OFF_AL + mi * 16 * ROWB);
                #pragma unroll
                for (int ni = 0; ni < 4; ni++)
                    mma16816(acc[mi][ni], ah, bh[ni][0], bh[ni][1]);
                #pragma unroll
                for (int ni = 0; ni < 4; ni++)
                    mma16816(acc[mi][ni], al, bh[ni][0], bh[ni][1]);
                #pragma unroll
                for (int ni = 0; ni < 4; ni++)
                    mma16816(acc[mi][ni], ah, bl[ni][0], bl[ni][1]);
            }
        }

        // ---- STS chunk ci+1 into other buffer (R9 position) ----
        if (ci + 1 < nch) {
            char* st = smem + ((ci + 1) & 1) * STAGE_B;
            #pragma unroll
            for (int it = 0; it < 2; it++) {
                int row = lrow + it * 64;
                uint32_t off = (uint32_t)(row * ROWB + lq * 8);
                uint32_t hw0, lw0, hw1, lw1;
                split_pair(pa[it].x, pa[it].y, hw0, lw0);
                split_pair(pa[it].z, pa[it].w, hw1, lw1);
                *reinterpret_cast<uint2*>(st + OFF_AH + off) = make_uint2(hw0, hw1);
                *reinterpret_cast<uint2*>(st + OFF_AL + off) = make_uint2(lw0, lw1);
                split_pair(pb[it].x, pb[it].y, hw0, lw0);
                split_pair(pb[it].z, pb[it].w, hw1, lw1);
                *reinterpret_cast<uint2*>(st + OFF_BH + off) = make_uint2(hw0, hw1);
                *reinterpret_cast<uint2*>(st + OFF_BL + off) = make_uint2(lw0, lw1);
            }
            if (do_rn) {
                rn0 += pb[0].x * pb[0].x + pb[0].y * pb[0].y + pb[0].z * pb[0].z + pb[0].w * pb[0].w;
                rn1 += pb[1].x * pb[1].x + pb[1].y * pb[1].y + pb[1].z * pb[1].z + pb[1].w * pb[1].w;
            }
        }
    }

    // ---- fused row-norm output (encoder, bm slice 0 only) ----
    if (do_rn) {
        rn0 += __shfl_xor_sync(0xffffffffu, rn0, 1);
        rn0 += __shfl_xor_sync(0xffffffffu, rn0, 2);
        rn1 += __shfl_xor_sync(0xffffffffu, rn1, 1);
        rn1 += __shfl_xor_sync(0xffffffffu, rn1, 2);
        if (lq == 0) {
            int r0 = bn + lrow, r1 = bn + lrow + 64;
            if (r0 < N) atomicAdd(&g_rownorm2[r0], rn0);
            if (r1 < N) atomicAdd(&g_rownorm2[r1], rn1);
        }
    }

    // ---- epilogue: raw f32 partial into split-K slab ----
    const int er = lane >> 2, ec = (lane & 3) * 2;
    float* Cz = C + (size_t)z * BATCH * ldc;
    #pragma unroll
    for (int mi = 0; mi < 4; mi++) {
        #pragma unroll
        for (int ni = 0; ni < 4; ni++) {
            int m0 = bm + wm * 64 + mi * 16 + er;
            int n0 = bn + wn * 32 + ni * 8 + ec;
            if (n0 + 1 < N) {
                *reinterpret_cast<float2*>(Cz + (size_t)m0 * ldc + n0) =
                    make_float2(acc[mi][ni][0], acc[mi][ni][1]);
                *reinterpret_cast<float2*>(Cz + (size_t)(m0 + 8) * ldc + n0) =
                    make_float2(acc[mi][ni][2], acc[mi][ni][3]);
            } else if (n0 < N) {
                Cz[(size_t)m0 * ldc + n0] = acc[mi][ni][0];
                Cz[(size_t)(m0 + 8) * ldc + n0] = acc[mi][ni][2];
            }
        }
    }
}

// ---------------------------------------------------------------------------
// zero row-norm accumulators + jac
// ---------------------------------------------------------------------------
__global__ void init_misc(float* __restrict__ jac_init) {
    int i = blockIdx.x * 256 + threadIdx.x;
    if (i < FEAT) g_rownorm2[i] = 0.f;
    if (i == 0) *jac_init = 0.f;
}

// ---------------------------------------------------------------------------
// encoder epilogue: sum split-K partials + bias -> sigmoid -> y_enc (padded),
// accumulate jac_reg (row norms came from the fused encoder GEMM)
// ---------------------------------------------------------------------------
__global__ void enc_epilogue(const float* __restrict__ b_enc, float* __restrict__ jac_out) {
    int idx = blockIdx.x * blockDim.x + threadIdx.x;
    float part = 0.f;
    if (idx < BATCH * FEAT_PAD) {
        int m = idx / FEAT_PAD, f = idx % FEAT_PAD;
        if (f < FEAT) {
            float zsum = b_enc[f];
            int base = m * FEAT + f;
            #pragma unroll
            for (int s = 0; s < SPLITK; s++)
                zsum += g_preact[(size_t)s * BATCH * FEAT + base];
            float y = sigmoidf_(zsum);
            g_yenc[idx] = y;
            float sd = y * (1.f - y);
            part = sd * sd * g_rownorm2[f];
        } else {
            g_yenc[idx] = 0.f;  // zero pad for decoder K
        }
    }
    #pragma unroll
    for (int o = 16; o > 0; o >>= 1) part += __shfl_down_sync(0xffffffffu, part, o);
    __shared__ float wsum[8];
    int lane = threadIdx.x & 31, wid = threadIdx.x >> 5;
    if (lane == 0) wsum[wid] = part;
    __syncthreads();
    if (wid == 0) {
        float v = (lane < 8) ? wsum[lane] : 0.f;
        #pragma unroll
        for (int o = 4; o > 0; o >>= 1) v += __shfl_down_sync(0xffffffffu, v, o);
        if (lane == 0) atomicAdd(jac_out, v);
    }
}

// ---------------------------------------------------------------------------
// decoder epilogue: sum DEC_SPLITK partials + bias -> sigmoid -> out (float4)
// ---------------------------------------------------------------------------
__global__ void dec_epilogue(const float* __restrict__ b_dec, float* __restrict__ out) {
    int i = blockIdx.x * blockDim.x + threadIdx.x;     // float4 group index
    if (i >= BATCH * INSZ / 4) return;
    int col4 = i % (INSZ / 4);
    float4 p0 = reinterpret_cast<const float4*>(g_dpart)[i];
    float4 p1 = reinterpret_cast<const float4*>(g_dpart + (size_t)BATCH * INSZ)[i];
    float4 b  = reinterpret_cast<const float4*>(b_dec)[col4];
    float4 r;
    r.x = sigmoidf_(p0.x + p1.x + b.x);
    r.y = sigmoidf_(p0.y + p1.y + b.y);
    r.z = sigmoidf_(p0.z + p1.z + b.z);
    r.w = sigmoidf_(p0.w + p1.w + b.w);
    reinterpret_cast<float4*>(out)[i] = r;
}

// ---------------------------------------------------------------------------
extern "C" void kernel_launch(void* const* d_in, const int* in_sizes, int n_in,
                              void* d_out, int out_size) {
    const float* x     = (const float*)d_in[0];
    const float* W_enc = (const float*)d_in[1];
    const float* b_enc = (const float*)d_in[2];
    const float* W_dec = (const float*)d_in[3];
    const float* b_dec = (const float*)d_in[4];
    float* out = (float*)d_out;
    float* jac = out + (out_size - 1);

    float *preact, *yenc, *dpart;
    cudaGetSymbolAddress((void**)&preact, g_preact);
    cudaGetSymbolAddress((void**)&yenc,  g_yenc);
    cudaGetSymbolAddress((void**)&dpart, g_dpart);

    cudaFuncSetAttribute(gemm_hmma<0>, cudaFuncAttributeMaxDynamicSharedMemorySize, SMEM_TOTAL);
    cudaFuncSetAttribute(gemm_hmma<2>, cudaFuncAttributeMaxDynamicSharedMemorySize, SMEM_TOTAL);

    // 1) zero rownorm accumulators + jac
    init_misc<<<(FEAT + 255) / 256, 256>>>(jac);

    // 2) encoder GEMM (fused W_enc row norms): split-K=12 -> 288 CTAs (~1 wave)
    {
        dim3 grid((FEAT + BN - 1) / BN, BATCH / BM, SPLITK);   // (12, 2, 12)
        gemm_hmma<0><<<grid, NTH, SMEM_TOTAL>>>(
            x, W_enc, nullptr, preact,
            FEAT, INSZ, INSZ, INSZ, FEAT,
            ENC_KBLK_PER_SPLIT, ENC_KBLK_TOTAL);
    }

    // 3) bias + sigmoid -> y_enc (padded); jacobian reduction
    enc_epilogue<<<(BATCH * FEAT_PAD + 255) / 256, 256>>>(b_enc, jac);

    // 4) decoder GEMM, split-K=2 -> 884 CTAs (~3 full waves, packed tail)
    {
        dim3 grid((INSZ + BN - 1) / BN, BATCH / BM, DEC_SPLITK);   // (221, 2, 2)
        gemm_hmma<2><<<grid, NTH, SMEM_TOTAL>>>(
            yenc, W_dec, nullptr, dpart,
            INSZ, FEAT_PAD, FEAT, FEAT, INSZ,
            DEC_KBLK_PER_SPLIT, DEC_KBLK_TOTAL);
    }

    // 5) sum decoder partials + bias -> sigmoid -> out
    dec_epilogue<<<(BATCH * INSZ / 4 + 255) / 256, 256>>>(b_dec, out);
}